// round 12
// baseline (speedup 1.0000x reference)
#include <cuda_runtime.h>
#include <math.h>

#define N_NODES 200000
#define N_EDGES 1000000
#define HDIM    64
#define NGRAPH  512
#define NCLS    10
#define BN_EPS  1e-5f

#define SCAN_CHUNK 1024
#define SCAN_BLKS  ((N_NODES + SCAN_CHUNK - 1) / SCAN_CHUNK)   // 196
#define NBUCKET 64
#define PSUM_STRIDE (NBUCKET * 2 * HDIM)            // 8192 doubles per layer
#define ADJ_TOTAL (N_EDGES + 3 * N_NODES)           // padded adjacency capacity

typedef unsigned long long ull;
#define PACKF(d, x)    asm("mov.b64 %0, {%1, %1};" : "=l"(d) : "f"(x))
#define UNPACK2(l,h,v) asm("mov.b64 {%0, %1}, %2;" : "=f"(l), "=f"(h) : "l"(v))
#define FMA2(d, a, b)  asm("fma.rn.f32x2 %0, %1, %2, %0;" : "+l"(d) : "l"(a), "l"(b))

// ---------------- static device scratch ----------------
__device__ __align__(256) float  g_buf1[(size_t)(N_NODES + 1) * HDIM]; // h' (row N = 0)
__device__ __align__(256) float  g_buf2[(size_t)N_NODES * HDIM];       // AGG layer 1
__device__ __align__(256) float  g_buf3[(size_t)N_NODES * HDIM];       // AGG layer 2
__device__ __align__(256) int    g_adj[ADJ_TOTAL];
__device__ __align__(256) int    g_cnt[N_NODES];
__device__ __align__(256) int2   g_row2[N_NODES];                      // {rowstart, cnt_padded}
__device__ __align__(256) int    g_cursor[N_NODES];
__device__ __align__(256) int    g_localex[N_NODES];
__device__ __align__(16)  int    g_blksum[256];
__device__ __align__(256) float  g_dinv[N_NODES];
__device__ __align__(256) double g_psums[2 * PSUM_STRIDE];             // [layer][bucket][128]
__device__ __align__(16)  float  g_scale[HDIM];
__device__ __align__(16)  float  g_shift[HDIM];

// ---------------- init: dummy-fill adj, zero counts/psums/zero-row ----------------
__global__ void init_kernel(int4* __restrict__ adj4, int* __restrict__ cnt,
                            double* __restrict__ psums, float* __restrict__ buf1) {
    int i = blockIdx.x * blockDim.x + threadIdx.x;
    if (i < ADJ_TOTAL / 4) adj4[i] = make_int4(N_NODES, N_NODES, N_NODES, N_NODES);
    if (i < N_NODES) cnt[i] = 0;
    if (i < 2 * PSUM_STRIDE) psums[i] = 0.0;
    if (i < HDIM) buf1[(size_t)N_NODES * HDIM + i] = 0.0f;  // zero row for dummies
}

__global__ void deg_count_kernel(const int* __restrict__ dst, int* __restrict__ cnt) {
    int i = blockIdx.x * blockDim.x + threadIdx.x;
    if (i >= N_EDGES / 4) return;
    int4 d = __ldg((const int4*)dst + i);
    atomicAdd(&cnt[d.x], 1);
    atomicAdd(&cnt[d.y], 1);
    atomicAdd(&cnt[d.z], 1);
    atomicAdd(&cnt[d.w], 1);
}

__global__ void dinv_kernel(const int* __restrict__ cnt, float* __restrict__ dinv) {
    int i = blockIdx.x * blockDim.x + threadIdx.x;
    if (i < N_NODES) dinv[i] = rsqrtf((float)(cnt[i] + 1));
}

// ---------------- scan over PADDED counts ----------------
__global__ void scanA_kernel(const int* __restrict__ cnt, int* __restrict__ localex,
                             int* __restrict__ blksum) {
    __shared__ int sh[256];
    int b = blockIdx.x, t = threadIdx.x;
    int base = b * SCAN_CHUNK + t * 4;
    int v0 = (base + 0 < N_NODES) ? ((cnt[base + 0] + 3) & ~3) : 0;
    int v1 = (base + 1 < N_NODES) ? ((cnt[base + 1] + 3) & ~3) : 0;
    int v2 = (base + 2 < N_NODES) ? ((cnt[base + 2] + 3) & ~3) : 0;
    int v3 = (base + 3 < N_NODES) ? ((cnt[base + 3] + 3) & ~3) : 0;
    int s = v0 + v1 + v2 + v3;
    sh[t] = s;
    __syncthreads();
#pragma unroll
    for (int off = 1; off < 256; off <<= 1) {
        int x = (t >= off) ? sh[t - off] : 0;
        __syncthreads();
        sh[t] += x;
        __syncthreads();
    }
    int excl = sh[t] - s;
    if (t == 255) blksum[b] = sh[255];
    if (base + 0 < N_NODES) localex[base + 0] = excl;  excl += v0;
    if (base + 1 < N_NODES) localex[base + 1] = excl;  excl += v1;
    if (base + 2 < N_NODES) localex[base + 2] = excl;  excl += v2;
    if (base + 3 < N_NODES) localex[base + 3] = excl;
}

__global__ void scanC_kernel(const int* __restrict__ localex, const int* __restrict__ blksum,
                             const int* __restrict__ cnt,
                             int2* __restrict__ row2, int* __restrict__ cursor) {
    __shared__ int sh[256];
    __shared__ int pre[256];
    int t = threadIdx.x;
    int v = (t < SCAN_BLKS) ? blksum[t] : 0;
    sh[t] = v;
    __syncthreads();
#pragma unroll
    for (int off = 1; off < 256; off <<= 1) {
        int x = (t >= off) ? sh[t - off] : 0;
        __syncthreads();
        sh[t] += x;
        __syncthreads();
    }
    pre[t] = sh[t] - v;
    __syncthreads();

    int i = blockIdx.x * 256 + t;
    if (i < N_NODES) {
        int c = cnt[i];
        int r = localex[i] + pre[i >> 10];
        row2[i] = make_int2(r, (c + 3) & ~3);
        cursor[i] = r;
    }
}

__global__ void scatter_kernel(const int* __restrict__ src, const int* __restrict__ dst,
                               int* __restrict__ cursor, int* __restrict__ adj) {
    int i = blockIdx.x * blockDim.x + threadIdx.x;
    if (i >= N_EDGES / 4) return;
    int4 s = __ldg((const int4*)src + i);
    int4 d = __ldg((const int4*)dst + i);
    adj[atomicAdd(&cursor[d.x], 1)] = s.x;
    adj[atomicAdd(&cursor[d.y], 1)] = s.y;
    adj[atomicAdd(&cursor[d.z], 1)] = s.z;
    adj[atomicAdd(&cursor[d.w], 1)] = s.w;
}

// ---------------- 64x64 GEMM, packed f32x2 FMA, 4x4 tiles ----------------
// 256 threads: tr=tid>>4 (rows 4tr..+3), tc=tid&15 (cols 4tc..+3).
// X stored dup'd in smem ((x,x) ull) with XOR swizzle: slot(r,k) = r ^ 4*(k&3).
// Mainloop: 3 LDS.128 + 8 FMA2 per k — zero packing. Output h' = (X@W)*dinv.
template <bool APPLY_BN>
__global__ void __launch_bounds__(256) gemm64_kernel(
        const float* __restrict__ X, const float* __restrict__ W,
        const float* __restrict__ dinv,
        const float* __restrict__ scale, const float* __restrict__ shift,
        float* __restrict__ HP) {
    __shared__ __align__(16) ull   Xd[64 * 64];   // [k][slot] dup pairs, 32KB
    __shared__ __align__(16) float Ws[64 * 64];   // [k][col], 16KB   (total = 48KB exact)

    int tid  = threadIdx.x;
    int row0 = blockIdx.x * 64;

    const float4* W4 = (const float4*)W;
#pragma unroll
    for (int j = 0; j < 4; j++)
        ((float4*)Ws)[tid + j * 256] = W4[tid + j * 256];

    const float4* X4 = (const float4*)(X + (size_t)row0 * 64);
#pragma unroll
    for (int j = 0; j < 4; j++) {
        int idx4 = tid + j * 256;          // 0..1023
        int r  = idx4 >> 4;                // 0..63
        int c4 = idx4 & 15;                // float4-chunk of cols
        float4 v = X4[idx4];
        if (APPLY_BN) {
            float4 sc = __ldg((const float4*)scale + c4);
            float4 sh = __ldg((const float4*)shift + c4);
            v.x = fmaxf(fmaf(v.x, sc.x, sh.x), 0.0f);
            v.y = fmaxf(fmaf(v.y, sc.y, sh.y), 0.0f);
            v.z = fmaxf(fmaf(v.z, sc.z, sh.z), 0.0f);
            v.w = fmaxf(fmaf(v.w, sc.w, sh.w), 0.0f);
        }
#pragma unroll
        for (int i = 0; i < 4; i++) {       // rotated store: 4-way max conflict
            int ii = (i + c4) & 3;
            float e = (ii == 0) ? v.x : (ii == 1) ? v.y : (ii == 2) ? v.z : v.w;
            int k = 4 * c4 + ii;
            ull d; PACKF(d, e);
            Xd[k * 64 + (r ^ ((k & 3) << 2))] = d;
        }
    }
    __syncthreads();

    int tr = tid >> 4, tc = tid & 15;
    ull acc[4][2];
#pragma unroll
    for (int i = 0; i < 4; i++) { acc[i][0] = 0ULL; acc[i][1] = 0ULL; }

#pragma unroll 16
    for (int k = 0; k < 64; k++) {
        const ulonglong2* xp =
            (const ulonglong2*)&Xd[k * 64 + 4 * (tr ^ (k & 3))];
        ulonglong2 xA = xp[0];   // rows 4tr+0, 4tr+1 (dup pairs)
        ulonglong2 xB = xp[1];   // rows 4tr+2, 4tr+3
        ulonglong2 wv = *(const ulonglong2*)&Ws[k * 64 + 4 * tc];  // col pairs
        FMA2(acc[0][0], xA.x, wv.x); FMA2(acc[0][1], xA.x, wv.y);
        FMA2(acc[1][0], xA.y, wv.x); FMA2(acc[1][1], xA.y, wv.y);
        FMA2(acc[2][0], xB.x, wv.x); FMA2(acc[2][1], xB.x, wv.y);
        FMA2(acc[3][0], xB.y, wv.x); FMA2(acc[3][1], xB.y, wv.y);
    }

#pragma unroll
    for (int i = 0; i < 4; i++) {
        int row = row0 + 4 * tr + i;
        float d = __ldg(dinv + row);
        float c0, c1, c2, c3;
        UNPACK2(c0, c1, acc[i][0]);
        UNPACK2(c2, c3, acc[i][1]);
        float4 o;
        o.x = c0 * d; o.y = c1 * d; o.z = c2 * d; o.w = c3 * d;
        *(float4*)&HP[(size_t)row * 64 + 4 * tc] = o;
    }
}

// ---------------- CSR gather agg (padded, int4 idx) + fused BN stats ----------------
__global__ void __launch_bounds__(256) agg_kernel(
        const int2* __restrict__ row2, const int* __restrict__ adj,
        const float* __restrict__ dinv,
        const float* __restrict__ HP, float* __restrict__ AGG,
        double* __restrict__ psums) {
    int tid  = threadIdx.x;
    int node = blockIdx.x * 16 + (tid >> 4);
    int part = tid & 15;
    const float4* Hp = (const float4*)HP;

    float4 acc = __ldg(Hp + (size_t)node * 16 + part);   // self h' (pre-scaled)
    int2 rc = __ldg(row2 + node);
    const int4* ap = (const int4*)(adj + rc.x);
    int nIt = rc.y >> 2;
    for (int it = 0; it < nIt; it++) {
        int4 s4 = __ldg(ap + it);
        float4 a = __ldg(Hp + (size_t)s4.x * 16 + part);
        float4 b = __ldg(Hp + (size_t)s4.y * 16 + part);
        float4 c = __ldg(Hp + (size_t)s4.z * 16 + part);
        float4 e = __ldg(Hp + (size_t)s4.w * 16 + part);
        acc.x += (a.x + b.x) + (c.x + e.x);
        acc.y += (a.y + b.y) + (c.y + e.y);
        acc.z += (a.z + b.z) + (c.z + e.z);
        acc.w += (a.w + b.w) + (c.w + e.w);
    }
    float dd = __ldg(dinv + node);
    acc.x *= dd; acc.y *= dd; acc.z *= dd; acc.w *= dd;
    ((float4*)AGG)[(size_t)node * 16 + part] = acc;

    __shared__ float4 s_acc[256];
    s_acc[tid] = acc;
    __syncthreads();
    if (tid < HDIM) {
        const float* sa = (const float*)s_acc;
        float s = 0.0f, sq = 0.0f;
#pragma unroll
        for (int n = 0; n < 16; n++) {
            float v = sa[n * 64 + tid];
            s += v;
            sq += v * v;
        }
        int bucket = blockIdx.x & (NBUCKET - 1);
        atomicAdd(&psums[bucket * 128 + tid], (double)s);
        atomicAdd(&psums[bucket * 128 + HDIM + tid], (double)sq);
    }
}

// ---------------- layer-1 BN finalize ----------------
__global__ void bn_finalize_kernel(const double* __restrict__ psums,
                                   const float* __restrict__ g, const float* __restrict__ be,
                                   float* __restrict__ scale, float* __restrict__ shift) {
    int f = threadIdx.x;
    if (f >= HDIM) return;
    double s = 0.0, sq = 0.0;
#pragma unroll 4
    for (int b = 0; b < NBUCKET; b++) {
        s  += psums[b * 128 + f];
        sq += psums[b * 128 + HDIM + f];
    }
    double mean = s / (double)N_NODES;
    double var  = sq / (double)N_NODES - mean * mean;
    float rs = rsqrtf((float)var + BN_EPS);
    float sc = rs * g[f];
    scale[f] = sc;
    shift[f] = (float)(-mean) * sc + be[f];
}

// ---------------- fused: BN2-finalize + BN1/BN2 apply + residual + pool + MLP head ----
__global__ void __launch_bounds__(512) poolhead_kernel(
        const float* __restrict__ AGG1, const float* __restrict__ AGG2,
        const float* __restrict__ scale1, const float* __restrict__ shift1,
        const double* __restrict__ psums2,
        const float* __restrict__ g2, const float* __restrict__ be2,
        const int* __restrict__ batch,
        const float* __restrict__ lw1, const float* __restrict__ lb1,
        const float* __restrict__ lw2, const float* __restrict__ lb2,
        float* __restrict__ out) {
    int g = blockIdx.x;
    int tid = threadIdx.x;

    __shared__ float sc2s[64], sh2s[64];
    __shared__ int s_start, s_end;

    if (tid >= 64 && tid < 128) {
        int f = tid - 64;
        double s = 0.0, sq = 0.0;
#pragma unroll 4
        for (int b = 0; b < NBUCKET; b++) {
            s  += psums2[b * 128 + f];
            sq += psums2[b * 128 + HDIM + f];
        }
        double mean = s / (double)N_NODES;
        double var  = sq / (double)N_NODES - mean * mean;
        float rs = rsqrtf((float)var + BN_EPS);
        float sc = rs * g2[f];
        sc2s[f] = sc;
        sh2s[f] = (float)(-mean) * sc + be2[f];
    }
    if (tid == 0) {
        int lo = 0, hi = N_NODES;
        while (lo < hi) { int mid = (lo + hi) >> 1; if (batch[mid] < g) lo = mid + 1; else hi = mid; }
        s_start = lo;
        hi = N_NODES;
        while (lo < hi) { int mid = (lo + hi) >> 1; if (batch[mid] < g + 1) lo = mid + 1; else hi = mid; }
        s_end = lo;
    }
    __syncthreads();

    int start = s_start, end = s_end;
    int f = tid & 63;
    int grp = tid >> 6;
    float sc1 = __ldg(scale1 + f), sh1 = __ldg(shift1 + f);
    float sc2 = sc2s[f],           sh2 = sh2s[f];
    float s = 0.0f;
#pragma unroll 2
    for (int r = start + grp; r < end; r += 8) {
        float a1 = AGG1[(size_t)r * 64 + f];
        float a2 = AGG2[(size_t)r * 64 + f];
        s += fmaxf(fmaf(a1, sc1, sh1), 0.0f) + fmaxf(fmaf(a2, sc2, sh2), 0.0f);
    }
    __shared__ float shm[512];
    shm[tid] = s;
    __syncthreads();

    __shared__ float p[64];
    if (grp == 0) {
        float t = 0.0f;
#pragma unroll
        for (int q = 0; q < 8; q++) t += shm[f + q * 64];
        int cnt = end - start;
        p[f] = t / (float)(cnt > 0 ? cnt : 1);
    }
    __syncthreads();

    __shared__ float z[32];
    __shared__ float lg[NCLS];
    if (tid < 32) {
        float acc = lb1[tid];
#pragma unroll
        for (int k = 0; k < 64; k++) acc += p[k] * lw1[k * 32 + tid];
        z[tid] = fmaxf(acc, 0.0f);
    }
    __syncthreads();
    if (tid < NCLS) {
        float acc = lb2[tid];
#pragma unroll
        for (int k = 0; k < 32; k++) acc += z[k] * lw2[k * 10 + tid];
        lg[tid] = acc;
    }
    __syncthreads();
    if (tid == 0) {
        float m = lg[0];
#pragma unroll
        for (int c = 1; c < NCLS; c++) m = fmaxf(m, lg[c]);
        float se = 0.0f;
#pragma unroll
        for (int c = 0; c < NCLS; c++) se += expf(lg[c] - m);
        float l = m + logf(se);
#pragma unroll
        for (int c = 0; c < NCLS; c++) out[g * NCLS + c] = lg[c] - l;
    }
}

// ---------------- host ----------------
extern "C" void kernel_launch(void* const* d_in, const int* in_sizes, int n_in,
                              void* d_out, int out_size) {
    const float* x     = (const float*)d_in[0];
    const int*   ei    = (const int*)  d_in[1];
    const int*   batch = (const int*)  d_in[2];
    const float* W1  = (const float*)d_in[3];
    // b1 (d_in[4]) cancels inside BatchNorm
    const float* g1  = (const float*)d_in[5];
    const float* be1 = (const float*)d_in[6];
    const float* W2  = (const float*)d_in[7];
    // b2 (d_in[8]) cancels
    const float* g2  = (const float*)d_in[9];
    const float* be2 = (const float*)d_in[10];
    const float* lw1 = (const float*)d_in[11];
    const float* lb1 = (const float*)d_in[12];
    const float* lw2 = (const float*)d_in[13];
    const float* lb2 = (const float*)d_in[14];

    const int* src = ei;
    const int* dst = ei + N_EDGES;

    float *buf1, *buf2, *buf3, *dinv, *scale, *shift;
    int *adj, *cnt, *cursor, *localex, *blksum;
    int2* row2;
    double* psums;
    cudaGetSymbolAddress((void**)&buf1,   g_buf1);
    cudaGetSymbolAddress((void**)&buf2,   g_buf2);
    cudaGetSymbolAddress((void**)&buf3,   g_buf3);
    cudaGetSymbolAddress((void**)&adj,    g_adj);
    cudaGetSymbolAddress((void**)&cnt,    g_cnt);
    cudaGetSymbolAddress((void**)&row2,   g_row2);
    cudaGetSymbolAddress((void**)&cursor, g_cursor);
    cudaGetSymbolAddress((void**)&localex,g_localex);
    cudaGetSymbolAddress((void**)&blksum, g_blksum);
    cudaGetSymbolAddress((void**)&dinv,   g_dinv);
    cudaGetSymbolAddress((void**)&psums,  g_psums);
    cudaGetSymbolAddress((void**)&scale,  g_scale);
    cudaGetSymbolAddress((void**)&shift,  g_shift);

    const int TB = 256;
    const int init_blk = (ADJ_TOTAL / 4 + TB - 1) / TB;  // 1563
    const int n_blk    = (N_NODES + TB - 1) / TB;        // 782
    const int e4_blk   = (N_EDGES / 4 + TB - 1) / TB;    // 977
    const int agg_blk  = N_NODES / 16;                   // 12500
    const int gemm_blk = N_NODES / 64;                   // 3125

    // ---- degrees first so gemm1 lands at launch idx 3 (the ncu profile slot) ----
    init_kernel     <<<init_blk, TB>>>((int4*)adj, cnt, psums, buf1);
    deg_count_kernel<<<e4_blk, TB>>>(dst, cnt);
    dinv_kernel     <<<n_blk, TB>>>(cnt, dinv);
    gemm64_kernel<false><<<gemm_blk, TB>>>(x, W1, dinv, nullptr, nullptr, buf1);
    scanA_kernel    <<<SCAN_BLKS, 256>>>(cnt, localex, blksum);
    scanC_kernel    <<<n_blk, 256>>>(localex, blksum, cnt, row2, cursor);
    scatter_kernel  <<<e4_blk, TB>>>(src, dst, cursor, adj);

    // ---- layer 1 ----
    agg_kernel          <<<agg_blk, TB>>>(row2, adj, dinv, buf1, buf2, psums);
    bn_finalize_kernel  <<<1, 64>>>(psums, g1, be1, scale, shift);

    // ---- layer 2 (BN1+relu fused into gemm input load) ----
    gemm64_kernel<true> <<<gemm_blk, TB>>>(buf2, W2, dinv, scale, shift, buf1);
    agg_kernel          <<<agg_blk, TB>>>(row2, adj, dinv, buf1, buf3, psums + PSUM_STRIDE);

    // ---- fused BN2-finalize + BN-apply(x2) + residual + pool + head ----
    poolhead_kernel<<<NGRAPH, 512>>>(buf2, buf3, scale, shift, psums + PSUM_STRIDE,
                                     g2, be2, batch, lw1, lb1, lw2, lb2, (float*)d_out);
}

// round 13
// speedup vs baseline: 1.1656x; 1.1656x over previous
#include <cuda_runtime.h>
#include <math.h>

#define N_NODES 200000
#define N_EDGES 1000000
#define HDIM    64
#define NGRAPH  512
#define NCLS    10
#define BN_EPS  1e-5f

#define SCAN_CHUNK 1024
#define SCAN_BLKS  ((N_NODES + SCAN_CHUNK - 1) / SCAN_CHUNK)   // 196
#define NBUCKET 64
#define PSUM_STRIDE (NBUCKET * 2 * HDIM)            // 8192 doubles per layer
#define ADJ_TOTAL (N_EDGES + 3 * N_NODES)           // padded adjacency capacity

// ---------------- static device scratch ----------------
__device__ __align__(256) float  g_buf1[(size_t)(N_NODES + 1) * HDIM]; // h' (row N = 0)
__device__ __align__(256) float  g_buf2[(size_t)N_NODES * HDIM];       // AGG layer 1
__device__ __align__(256) float  g_buf3[(size_t)N_NODES * HDIM];       // AGG layer 2
__device__ __align__(256) int    g_adj[ADJ_TOTAL];
__device__ __align__(256) int    g_cnt[N_NODES];
__device__ __align__(256) int2   g_row2[N_NODES];                      // {rowstart, cnt_padded}
__device__ __align__(256) int    g_cursor[N_NODES];
__device__ __align__(256) int    g_localex[N_NODES];
__device__ __align__(16)  int    g_blksum[256];
__device__ __align__(256) float  g_dinv[N_NODES];
__device__ __align__(256) double g_psums[2 * PSUM_STRIDE];             // [layer][bucket][128]
__device__ __align__(16)  float  g_scale[HDIM];
__device__ __align__(16)  float  g_shift[HDIM];
__device__ __align__(256) float  g_pool1[NGRAPH * HDIM];               // relu1 graph sums

// ---------------- init: dummy-fill adj, zero counts/psums/pool1/zero-row ----------------
__global__ void init_kernel(int4* __restrict__ adj4, int* __restrict__ cnt,
                            double* __restrict__ psums, float* __restrict__ pool1,
                            float* __restrict__ buf1) {
    int i = blockIdx.x * blockDim.x + threadIdx.x;
    if (i < ADJ_TOTAL / 4) adj4[i] = make_int4(N_NODES, N_NODES, N_NODES, N_NODES);
    if (i < N_NODES) cnt[i] = 0;
    if (i < 2 * PSUM_STRIDE) psums[i] = 0.0;
    if (i < NGRAPH * HDIM) pool1[i] = 0.0f;
    if (i < HDIM) buf1[(size_t)N_NODES * HDIM + i] = 0.0f;  // zero row for dummies
}

__global__ void deg_count_kernel(const int* __restrict__ dst, int* __restrict__ cnt) {
    int i = blockIdx.x * blockDim.x + threadIdx.x;
    if (i >= N_EDGES / 4) return;
    int4 d = __ldg((const int4*)dst + i);
    atomicAdd(&cnt[d.x], 1);
    atomicAdd(&cnt[d.y], 1);
    atomicAdd(&cnt[d.z], 1);
    atomicAdd(&cnt[d.w], 1);
}

// ---------------- scan over PADDED counts ----------------
__global__ void scanA_kernel(const int* __restrict__ cnt, int* __restrict__ localex,
                             int* __restrict__ blksum) {
    __shared__ int sh[256];
    int b = blockIdx.x, t = threadIdx.x;
    int base = b * SCAN_CHUNK + t * 4;
    int v0 = (base + 0 < N_NODES) ? ((cnt[base + 0] + 3) & ~3) : 0;
    int v1 = (base + 1 < N_NODES) ? ((cnt[base + 1] + 3) & ~3) : 0;
    int v2 = (base + 2 < N_NODES) ? ((cnt[base + 2] + 3) & ~3) : 0;
    int v3 = (base + 3 < N_NODES) ? ((cnt[base + 3] + 3) & ~3) : 0;
    int s = v0 + v1 + v2 + v3;
    sh[t] = s;
    __syncthreads();
#pragma unroll
    for (int off = 1; off < 256; off <<= 1) {
        int x = (t >= off) ? sh[t - off] : 0;
        __syncthreads();
        sh[t] += x;
        __syncthreads();
    }
    int excl = sh[t] - s;
    if (t == 255) blksum[b] = sh[255];
    if (base + 0 < N_NODES) localex[base + 0] = excl;  excl += v0;
    if (base + 1 < N_NODES) localex[base + 1] = excl;  excl += v1;
    if (base + 2 < N_NODES) localex[base + 2] = excl;  excl += v2;
    if (base + 3 < N_NODES) localex[base + 3] = excl;
}

// each block redundantly scans blksum, then finalizes its 256 nodes (+ dinv)
__global__ void scanC_kernel(const int* __restrict__ localex, const int* __restrict__ blksum,
                             const int* __restrict__ cnt,
                             int2* __restrict__ row2, int* __restrict__ cursor,
                             float* __restrict__ dinv) {
    __shared__ int sh[256];
    __shared__ int pre[256];
    int t = threadIdx.x;
    int v = (t < SCAN_BLKS) ? blksum[t] : 0;
    sh[t] = v;
    __syncthreads();
#pragma unroll
    for (int off = 1; off < 256; off <<= 1) {
        int x = (t >= off) ? sh[t - off] : 0;
        __syncthreads();
        sh[t] += x;
        __syncthreads();
    }
    pre[t] = sh[t] - v;
    __syncthreads();

    int i = blockIdx.x * 256 + t;
    if (i < N_NODES) {
        int c = cnt[i];
        int r = localex[i] + pre[i >> 10];
        row2[i] = make_int2(r, (c + 3) & ~3);   // padded count
        cursor[i] = r;
        dinv[i] = rsqrtf((float)(c + 1));
    }
}

__global__ void scatter_kernel(const int* __restrict__ src, const int* __restrict__ dst,
                               int* __restrict__ cursor, int* __restrict__ adj) {
    int i = blockIdx.x * blockDim.x + threadIdx.x;
    if (i >= N_EDGES / 4) return;
    int4 s = __ldg((const int4*)src + i);
    int4 d = __ldg((const int4*)dst + i);
    adj[atomicAdd(&cursor[d.x], 1)] = s.x;
    adj[atomicAdd(&cursor[d.y], 1)] = s.y;
    adj[atomicAdd(&cursor[d.z], 1)] = s.z;
    adj[atomicAdd(&cursor[d.w], 1)] = s.w;
}

// ---------------- 64x64 GEMM, 4x4 register tiles (champion config) ----------------
// 256 threads = 16x16; thread (tr,tc) computes rows 4tr..+3, cols 4tc..+3.
// APPLY_BN: input v = relu(BN1(X)) on load + fused residual pooling of relu1.
template <bool APPLY_BN>
__global__ void __launch_bounds__(256) gemm64_kernel(
        const float* __restrict__ X, const float* __restrict__ W,
        const float* __restrict__ dinv,
        const float* __restrict__ scale, const float* __restrict__ shift,
        const int* __restrict__ batch, float* __restrict__ pool1,
        float* __restrict__ HP) {
    __shared__ __align__(16) float Ws[64 * 64];   // [k][col]
    __shared__ __align__(16) float Xt[64 * 68];   // [k][row], stride 68
    __shared__ float Ds[64];
    __shared__ int sbatch[64];

    int tid  = threadIdx.x;
    int row0 = blockIdx.x * 64;

    float sc = 1.0f, sh = 0.0f;
    if (APPLY_BN) {
        sc = __ldg(scale + (tid & 63));
        sh = __ldg(shift + (tid & 63));
        if (tid < 64) sbatch[tid] = batch[row0 + tid];
    }

#pragma unroll
    for (int j = 0; j < 16; j++) Ws[tid + j * 256] = W[tid + j * 256];
#pragma unroll
    for (int j = 0; j < 16; j++) {
        int idx = tid + j * 256;
        float v = X[(size_t)row0 * 64 + idx];
        if (APPLY_BN) v = fmaxf(fmaf(v, sc, sh), 0.0f);
        Xt[(idx & 63) * 68 + (idx >> 6)] = v;   // transpose: Xt[k][row]
    }
    if (tid < 64) Ds[tid] = dinv[row0 + tid];
    __syncthreads();

    int tr = tid >> 4, tc = tid & 15;
    float acc[4][4];
#pragma unroll
    for (int i = 0; i < 4; i++)
#pragma unroll
        for (int j = 0; j < 4; j++) acc[i][j] = 0.0f;

#pragma unroll
    for (int k = 0; k < 64; k++) {
        float4 xv = *(const float4*)&Xt[k * 68 + 4 * tr];
        float4 wv = *(const float4*)&Ws[k * 64 + 4 * tc];
        acc[0][0] += xv.x * wv.x; acc[0][1] += xv.x * wv.y; acc[0][2] += xv.x * wv.z; acc[0][3] += xv.x * wv.w;
        acc[1][0] += xv.y * wv.x; acc[1][1] += xv.y * wv.y; acc[1][2] += xv.y * wv.z; acc[1][3] += xv.y * wv.w;
        acc[2][0] += xv.z * wv.x; acc[2][1] += xv.z * wv.y; acc[2][2] += xv.z * wv.z; acc[2][3] += xv.z * wv.w;
        acc[3][0] += xv.w * wv.x; acc[3][1] += xv.w * wv.y; acc[3][2] += xv.w * wv.z; acc[3][3] += xv.w * wv.w;
    }

#pragma unroll
    for (int i = 0; i < 4; i++) {
        int r = 4 * tr + i;
        float d = Ds[r];
        float4 o;
        o.x = acc[i][0] * d; o.y = acc[i][1] * d;
        o.z = acc[i][2] * d; o.w = acc[i][3] * d;
        *(float4*)&HP[(size_t)(row0 + r) * 64 + 4 * tc] = o;
    }

    if (APPLY_BN) {   // residual pooling: Xt[f][r] = relu1; batch sorted within block
        int f = tid & 63;
        int q = tid >> 6;          // 0..3, each handles 16 rows
        int r0 = q * 16;
        float s = 0.0f;
        int curg = sbatch[r0];
#pragma unroll
        for (int rr = 0; rr < 16; rr++) {
            int r = r0 + rr;
            int gg = sbatch[r];
            if (gg != curg) { atomicAdd(&pool1[curg * 64 + f], s); s = 0.0f; curg = gg; }
            s += Xt[f * 68 + r];
        }
        atomicAdd(&pool1[curg * 64 + f], s);
    }
}

// ---------------- CSR gather agg (padded, int4 idx, prefetched) + fused BN stats ------
__global__ void __launch_bounds__(256) agg_kernel(
        const int2* __restrict__ row2, const int* __restrict__ adj,
        const float* __restrict__ dinv,
        const float* __restrict__ HP, float* __restrict__ AGG,
        double* __restrict__ psums) {
    int tid  = threadIdx.x;
    int node = blockIdx.x * 16 + (tid >> 4);
    int part = tid & 15;
    const float4* Hp = (const float4*)HP;

    float4 acc = __ldg(Hp + (size_t)node * 16 + part);   // self h' (pre-scaled by dinv)
    int2 rc = __ldg(row2 + node);
    const int4* ap = (const int4*)(adj + rc.x);           // rowstart % 4 == 0
    int nIt = rc.y >> 2;
    if (nIt > 0) {
        int4 s4 = __ldg(ap);
        for (int it = 0; it < nIt; it++) {
            int4 nx = (it + 1 < nIt) ? __ldg(ap + it + 1) : s4;   // prefetch next idx
            float4 a = __ldg(Hp + (size_t)s4.x * 16 + part);
            float4 b = __ldg(Hp + (size_t)s4.y * 16 + part);
            float4 c = __ldg(Hp + (size_t)s4.z * 16 + part);
            float4 e = __ldg(Hp + (size_t)s4.w * 16 + part);
            acc.x += (a.x + b.x) + (c.x + e.x);
            acc.y += (a.y + b.y) + (c.y + e.y);
            acc.z += (a.z + b.z) + (c.z + e.z);
            acc.w += (a.w + b.w) + (c.w + e.w);
            s4 = nx;
        }
    }
    float dd = __ldg(dinv + node);
    acc.x *= dd; acc.y *= dd; acc.z *= dd; acc.w *= dd;
    ((float4*)AGG)[(size_t)node * 16 + part] = acc;

    // fused BN stats: block-reduce over 16 nodes, bucketed double atomics
    __shared__ float4 s_acc[256];
    s_acc[tid] = acc;
    __syncthreads();
    if (tid < HDIM) {
        const float* sa = (const float*)s_acc;
        float s = 0.0f, sq = 0.0f;
#pragma unroll
        for (int n = 0; n < 16; n++) {
            float v = sa[n * 64 + tid];
            s += v;
            sq += v * v;
        }
        int bucket = blockIdx.x & (NBUCKET - 1);
        atomicAdd(&psums[bucket * 128 + tid], (double)s);
        atomicAdd(&psums[bucket * 128 + HDIM + tid], (double)sq);
    }
}

// ---------------- layer-1 BN finalize ----------------
__global__ void bn_finalize_kernel(const double* __restrict__ psums,
                                   const float* __restrict__ g, const float* __restrict__ be,
                                   float* __restrict__ scale, float* __restrict__ shift) {
    int f = threadIdx.x;
    if (f >= HDIM) return;
    double s = 0.0, sq = 0.0;
#pragma unroll 4
    for (int b = 0; b < NBUCKET; b++) {
        s  += psums[b * 128 + f];
        sq += psums[b * 128 + HDIM + f];
    }
    double mean = s / (double)N_NODES;
    double var  = sq / (double)N_NODES - mean * mean;
    float rs = rsqrtf((float)var + BN_EPS);
    float sc = rs * g[f];
    scale[f] = sc;
    shift[f] = (float)(-mean) * sc + be[f];
}

// ---------------- fused: BN2-finalize + BN2 apply + pool2 + residual pool1 + head -----
__global__ void __launch_bounds__(512) poolhead_kernel(
        const float* __restrict__ AGG2, const float* __restrict__ pool1,
        const double* __restrict__ psums2,
        const float* __restrict__ g2, const float* __restrict__ be2,
        const int* __restrict__ batch,
        const float* __restrict__ lw1, const float* __restrict__ lb1,
        const float* __restrict__ lw2, const float* __restrict__ lb2,
        float* __restrict__ out) {
    int g = blockIdx.x;
    int tid = threadIdx.x;

    __shared__ float sc2s[64], sh2s[64];
    __shared__ int s_start, s_end;

    if (tid >= 64 && tid < 128) {
        int f = tid - 64;
        double s = 0.0, sq = 0.0;
#pragma unroll 4
        for (int b = 0; b < NBUCKET; b++) {
            s  += psums2[b * 128 + f];
            sq += psums2[b * 128 + HDIM + f];
        }
        double mean = s / (double)N_NODES;
        double var  = sq / (double)N_NODES - mean * mean;
        float rs = rsqrtf((float)var + BN_EPS);
        float sc = rs * g2[f];
        sc2s[f] = sc;
        sh2s[f] = (float)(-mean) * sc + be2[f];
    }
    if (tid == 0) {
        int lo = 0, hi = N_NODES;
        while (lo < hi) { int mid = (lo + hi) >> 1; if (batch[mid] < g) lo = mid + 1; else hi = mid; }
        s_start = lo;
        hi = N_NODES;
        while (lo < hi) { int mid = (lo + hi) >> 1; if (batch[mid] < g + 1) lo = mid + 1; else hi = mid; }
        s_end = lo;
    }
    __syncthreads();

    int start = s_start, end = s_end;
    int f = tid & 63;
    int grp = tid >> 6;
    float sc2 = sc2s[f], sh2 = sh2s[f];
    float s = 0.0f;
#pragma unroll 2
    for (int r = start + grp; r < end; r += 8) {
        float a2 = AGG2[(size_t)r * 64 + f];
        s += fmaxf(fmaf(a2, sc2, sh2), 0.0f);
    }
    __shared__ float shm[512];
    shm[tid] = s;
    __syncthreads();

    __shared__ float p[64];
    if (grp == 0) {
        float t = 0.0f;
#pragma unroll
        for (int q = 0; q < 8; q++) t += shm[f + q * 64];
        t += __ldg(pool1 + g * 64 + f);          // residual relu1 graph sum
        int cnt = end - start;
        p[f] = t / (float)(cnt > 0 ? cnt : 1);
    }
    __syncthreads();

    __shared__ float z[32];
    __shared__ float lg[NCLS];
    if (tid < 32) {
        float acc = lb1[tid];
#pragma unroll
        for (int k = 0; k < 64; k++) acc += p[k] * lw1[k * 32 + tid];
        z[tid] = fmaxf(acc, 0.0f);
    }
    __syncthreads();
    if (tid < NCLS) {
        float acc = lb2[tid];
#pragma unroll
        for (int k = 0; k < 32; k++) acc += z[k] * lw2[k * 10 + tid];
        lg[tid] = acc;
    }
    __syncthreads();
    if (tid == 0) {
        float m = lg[0];
#pragma unroll
        for (int c = 1; c < NCLS; c++) m = fmaxf(m, lg[c]);
        float se = 0.0f;
#pragma unroll
        for (int c = 0; c < NCLS; c++) se += expf(lg[c] - m);
        float l = m + logf(se);
#pragma unroll
        for (int c = 0; c < NCLS; c++) out[g * NCLS + c] = lg[c] - l;
    }
}

// ---------------- host ----------------
extern "C" void kernel_launch(void* const* d_in, const int* in_sizes, int n_in,
                              void* d_out, int out_size) {
    const float* x     = (const float*)d_in[0];
    const int*   ei    = (const int*)  d_in[1];
    const int*   batch = (const int*)  d_in[2];
    const float* W1  = (const float*)d_in[3];
    // b1 (d_in[4]) cancels inside BatchNorm
    const float* g1  = (const float*)d_in[5];
    const float* be1 = (const float*)d_in[6];
    const float* W2  = (const float*)d_in[7];
    // b2 (d_in[8]) cancels
    const float* g2  = (const float*)d_in[9];
    const float* be2 = (const float*)d_in[10];
    const float* lw1 = (const float*)d_in[11];
    const float* lb1 = (const float*)d_in[12];
    const float* lw2 = (const float*)d_in[13];
    const float* lb2 = (const float*)d_in[14];

    const int* src = ei;
    const int* dst = ei + N_EDGES;

    float *buf1, *buf2, *buf3, *dinv, *scale, *shift, *pool1;
    int *adj, *cnt, *cursor, *localex, *blksum;
    int2* row2;
    double* psums;
    cudaGetSymbolAddress((void**)&buf1,   g_buf1);
    cudaGetSymbolAddress((void**)&buf2,   g_buf2);
    cudaGetSymbolAddress((void**)&buf3,   g_buf3);
    cudaGetSymbolAddress((void**)&adj,    g_adj);
    cudaGetSymbolAddress((void**)&cnt,    g_cnt);
    cudaGetSymbolAddress((void**)&row2,   g_row2);
    cudaGetSymbolAddress((void**)&cursor, g_cursor);
    cudaGetSymbolAddress((void**)&localex,g_localex);
    cudaGetSymbolAddress((void**)&blksum, g_blksum);
    cudaGetSymbolAddress((void**)&dinv,   g_dinv);
    cudaGetSymbolAddress((void**)&psums,  g_psums);
    cudaGetSymbolAddress((void**)&scale,  g_scale);
    cudaGetSymbolAddress((void**)&shift,  g_shift);
    cudaGetSymbolAddress((void**)&pool1,  g_pool1);

    const int TB = 256;
    const int init_blk = (ADJ_TOTAL / 4 + TB - 1) / TB;  // 1563
    const int n_blk    = (N_NODES + TB - 1) / TB;        // 782
    const int e4_blk   = (N_EDGES / 4 + TB - 1) / TB;    // 977
    const int agg_blk  = N_NODES / 16;                   // 12500
    const int gemm_blk = N_NODES / 64;                   // 3125

    // ---- CSR build + norms ----
    init_kernel     <<<init_blk, TB>>>((int4*)adj, cnt, psums, pool1, buf1);
    deg_count_kernel<<<e4_blk, TB>>>(dst, cnt);
    scanA_kernel    <<<SCAN_BLKS, 256>>>(cnt, localex, blksum);
    scanC_kernel    <<<n_blk, 256>>>(localex, blksum, cnt, row2, cursor, dinv);
    scatter_kernel  <<<e4_blk, TB>>>(src, dst, cursor, adj);

    // ---- layer 1 ----
    gemm64_kernel<false><<<gemm_blk, TB>>>(x, W1, dinv, nullptr, nullptr,
                                           nullptr, nullptr, buf1);
    agg_kernel          <<<agg_blk, TB>>>(row2, adj, dinv, buf1, buf2, psums);
    bn_finalize_kernel  <<<1, 64>>>(psums, g1, be1, scale, shift);

    // ---- layer 2 (BN1+relu fused on input; residual pooling fused in epilogue) ----
    gemm64_kernel<true> <<<gemm_blk, TB>>>(buf2, W2, dinv, scale, shift,
                                           batch, pool1, buf1);
    agg_kernel          <<<agg_blk, TB>>>(row2, adj, dinv, buf1, buf3, psums + PSUM_STRIDE);

    // ---- fused BN2-finalize + apply + pool + head ----
    poolhead_kernel<<<NGRAPH, 512>>>(buf3, pool1, psums + PSUM_STRIDE,
                                     g2, be2, batch, lw1, lb1, lw2, lb2, (float*)d_out);
}

// round 15
// speedup vs baseline: 1.2805x; 1.0986x over previous
#include <cuda_runtime.h>
#include <cuda_bf16.h>
#include <math.h>

#define N_NODES 200000
#define N_EDGES 1000000
#define HDIM    64
#define NGRAPH  512
#define NCLS    10
#define BN_EPS  1e-5f

#define SCAN_CHUNK 1024
#define SCAN_BLKS  ((N_NODES + SCAN_CHUNK - 1) / SCAN_CHUNK)   // 196
#define NBUCKET 64
#define PSUM_STRIDE (NBUCKET * 2 * HDIM)            // 8192 doubles per layer
#define ADJ_TOTAL (N_EDGES + 3 * N_NODES)           // padded adjacency capacity

#define ASTRIDE 72      // bf16 elements per smem row (144B: conflict-free ldmatrix)

typedef unsigned int uint32;

// ---------------- static device scratch ----------------
__device__ __align__(256) float  g_buf1[(size_t)(N_NODES + 1) * HDIM]; // h' (row N = 0)
__device__ __align__(256) float  g_buf2[(size_t)N_NODES * HDIM];       // AGG layer 1
__device__ __align__(256) float  g_buf3[(size_t)N_NODES * HDIM];       // AGG layer 2
__device__ __align__(256) int    g_adj[ADJ_TOTAL];
__device__ __align__(256) int    g_cnt[N_NODES];
__device__ __align__(256) int2   g_row2[N_NODES];
__device__ __align__(256) int    g_cursor[N_NODES];
__device__ __align__(256) int    g_localex[N_NODES];
__device__ __align__(16)  int    g_blksum[256];
__device__ __align__(256) float  g_dinv[N_NODES];
__device__ __align__(256) double g_psums[2 * PSUM_STRIDE];
__device__ __align__(16)  float  g_scale[HDIM];
__device__ __align__(16)  float  g_shift[HDIM];
__device__ __align__(256) float  g_pool1[NGRAPH * HDIM];

// ---------------- warp-MMA helpers ----------------
__device__ __forceinline__ uint32 smem_u32(const void* p) {
    uint32 a;
    asm("{ .reg .u64 t; cvta.to.shared.u64 t, %1; cvt.u32.u64 %0, t; }" : "=r"(a) : "l"(p));
    return a;
}
#define LDSM4(r, addr) \
    asm volatile("ldmatrix.sync.aligned.m8n8.x4.shared.b16 {%0, %1, %2, %3}, [%4];" \
        : "=r"((r)[0]), "=r"((r)[1]), "=r"((r)[2]), "=r"((r)[3]) : "r"(addr))
#define MMA16816(c, a, b0, b1) \
    asm volatile("mma.sync.aligned.m16n8k16.row.col.f32.bf16.bf16.f32 " \
        "{%0, %1, %2, %3}, {%4, %5, %6, %7}, {%8, %9}, {%0, %1, %2, %3};" \
        : "+f"((c)[0]), "+f"((c)[1]), "+f"((c)[2]), "+f"((c)[3]) \
        : "r"((a)[0]), "r"((a)[1]), "r"((a)[2]), "r"((a)[3]), "r"(b0), "r"(b1))

// ---------------- init ----------------
__global__ void init_kernel(int4* __restrict__ adj4, int* __restrict__ cnt,
                            double* __restrict__ psums, float* __restrict__ pool1,
                            float* __restrict__ buf1) {
    int i = blockIdx.x * blockDim.x + threadIdx.x;
    if (i < ADJ_TOTAL / 4) adj4[i] = make_int4(N_NODES, N_NODES, N_NODES, N_NODES);
    if (i < N_NODES) cnt[i] = 0;
    if (i < 2 * PSUM_STRIDE) psums[i] = 0.0;
    if (i < NGRAPH * HDIM) pool1[i] = 0.0f;
    if (i < HDIM) buf1[(size_t)N_NODES * HDIM + i] = 0.0f;  // zero row for dummies
}

__global__ void deg_count_kernel(const int* __restrict__ dst, int* __restrict__ cnt) {
    int i = blockIdx.x * blockDim.x + threadIdx.x;
    if (i >= N_EDGES / 4) return;
    int4 d = __ldg((const int4*)dst + i);
    atomicAdd(&cnt[d.x], 1);
    atomicAdd(&cnt[d.y], 1);
    atomicAdd(&cnt[d.z], 1);
    atomicAdd(&cnt[d.w], 1);
}

__global__ void dinv_kernel(const int* __restrict__ cnt, float* __restrict__ dinv) {
    int i = blockIdx.x * blockDim.x + threadIdx.x;
    if (i < N_NODES) dinv[i] = rsqrtf((float)(cnt[i] + 1));
}

// ---------------- HMMA GEMM: HP = (X@W)*dinv, bf16 3-product split ----------------
// 256 threads = 8 warps; warp w: mtile = w>>1 (16 rows), ntiles (w&1)*4..+3 (32 cols).
// APPLY_BN: X := relu(BN1(X)) on load + fused residual pooling into pool1.
template <bool APPLY_BN>
__global__ void __launch_bounds__(256) gemm_hmma_kernel(
        const float* __restrict__ X, const float* __restrict__ W,
        const float* __restrict__ dinv,
        const float* __restrict__ scale, const float* __restrict__ shift,
        const int* __restrict__ batch, float* __restrict__ pool1,
        float* __restrict__ HP) {
    __shared__ __align__(16) __nv_bfloat16 Ah[64 * ASTRIDE];
    __shared__ __align__(16) __nv_bfloat16 Al[64 * ASTRIDE];
    __shared__ __align__(16) __nv_bfloat16 Bh[64 * ASTRIDE];   // Wt[n][k]
    __shared__ __align__(16) __nv_bfloat16 Bl[64 * ASTRIDE];
    __shared__ int sbatch[64];

    int tid  = threadIdx.x;
    int row0 = blockIdx.x * 64;   // 200000 = 64*3125 exact, no bounds needed

    // W[k][n] -> Bh/Bl[n][k] (bf16 hi/lo split)
#pragma unroll
    for (int j = 0; j < 16; j++) {
        int idx = tid + j * 256;
        int k = idx >> 6, n = idx & 63;
        float w = __ldg(W + idx);
        __nv_bfloat16 h = __float2bfloat16(w);
        __nv_bfloat16 l = __float2bfloat16(w - __bfloat162float(h));
        Bh[n * ASTRIDE + k] = h;
        Bl[n * ASTRIDE + k] = l;
    }

    // X tile (64 rows) -> Ah/Al, optional BN1+relu
    float4 sc4, sh4;
    if (APPLY_BN) {
        sc4 = __ldg((const float4*)scale + (tid & 15));
        sh4 = __ldg((const float4*)shift + (tid & 15));
        if (tid < 64) sbatch[tid] = batch[row0 + tid];
    }
#pragma unroll
    for (int j = 0; j < 4; j++) {
        int idx4 = tid + j * 256;          // 0..1023
        int r = idx4 >> 4, c4 = idx4 & 15;
        float4 v = __ldg((const float4*)X + (size_t)row0 * 16 + idx4);
        if (APPLY_BN) {
            v.x = fmaxf(fmaf(v.x, sc4.x, sh4.x), 0.0f);
            v.y = fmaxf(fmaf(v.y, sc4.y, sh4.y), 0.0f);
            v.z = fmaxf(fmaf(v.z, sc4.z, sh4.z), 0.0f);
            v.w = fmaxf(fmaf(v.w, sc4.w, sh4.w), 0.0f);
        }
        __nv_bfloat16 hx = __float2bfloat16(v.x), hy = __float2bfloat16(v.y);
        __nv_bfloat16 hz = __float2bfloat16(v.z), hw = __float2bfloat16(v.w);
        __nv_bfloat162 h01; h01.x = hx; h01.y = hy;
        __nv_bfloat162 h23; h23.x = hz; h23.y = hw;
        __nv_bfloat162 l01, l23;
        l01.x = __float2bfloat16(v.x - __bfloat162float(hx));
        l01.y = __float2bfloat16(v.y - __bfloat162float(hy));
        l23.x = __float2bfloat16(v.z - __bfloat162float(hz));
        l23.y = __float2bfloat16(v.w - __bfloat162float(hw));
        int e = r * ASTRIDE + c4 * 4;
        *(__nv_bfloat162*)&Ah[e]     = h01;
        *(__nv_bfloat162*)&Ah[e + 2] = h23;
        *(__nv_bfloat162*)&Al[e]     = l01;
        *(__nv_bfloat162*)&Al[e + 2] = l23;
    }
    __syncthreads();

    int wid = tid >> 5, lane = tid & 31;
    int mt = wid >> 1;            // 0..3
    int nb = (wid & 1) * 4;       // ntile base (cols nb*8)

    // lane-dependent smem byte addresses (add ks*32 per k-step)
    uint32 aH = smem_u32(Ah) + ((mt * 16 + (lane & 15)) * ASTRIDE + ((lane >> 4) << 3)) * 2;
    uint32 aL = aH + (uint32)(Al - Ah) * 2;
    int quad = lane >> 3;
    uint32 bRow = (nb * 8 + ((quad >> 1) << 3) + (lane & 7)) * ASTRIDE + ((quad & 1) << 3);
    uint32 bH1 = smem_u32(Bh) + bRow * 2;
    uint32 bH2 = bH1 + 16 * ASTRIDE * 2;
    uint32 bL1 = smem_u32(Bl) + bRow * 2;
    uint32 bL2 = bL1 + 16 * ASTRIDE * 2;

    float c[4][4];
#pragma unroll
    for (int i = 0; i < 4; i++)
#pragma unroll
        for (int j = 0; j < 4; j++) c[i][j] = 0.0f;

#pragma unroll
    for (int ks = 0; ks < 4; ks++) {
        uint32 ko = ks * 32;   // 16 bf16 = 32 bytes
        uint32 ah[4], al[4], bh01[4], bh23[4], bl01[4], bl23[4];
        LDSM4(ah, aH + ko);
        LDSM4(al, aL + ko);
        LDSM4(bh01, bH1 + ko);
        LDSM4(bh23, bH2 + ko);
        LDSM4(bl01, bL1 + ko);
        LDSM4(bl23, bL2 + ko);
        // Ah @ Bh
        MMA16816(c[0], ah, bh01[0], bh01[1]);
        MMA16816(c[1], ah, bh01[2], bh01[3]);
        MMA16816(c[2], ah, bh23[0], bh23[1]);
        MMA16816(c[3], ah, bh23[2], bh23[3]);
        // Ah @ Bl
        MMA16816(c[0], ah, bl01[0], bl01[1]);
        MMA16816(c[1], ah, bl01[2], bl01[3]);
        MMA16816(c[2], ah, bl23[0], bl23[1]);
        MMA16816(c[3], ah, bl23[2], bl23[3]);
        // Al @ Bh
        MMA16816(c[0], al, bh01[0], bh01[1]);
        MMA16816(c[1], al, bh01[2], bh01[3]);
        MMA16816(c[2], al, bh23[0], bh23[1]);
        MMA16816(c[3], al, bh23[2], bh23[3]);
    }

    // epilogue: scale by dinv[row], store float2 per accum pair
    int qr = lane >> 2;           // 0..7
    int qc = (lane & 3) * 2;
    int rlo = row0 + mt * 16 + qr;
    int rhi = rlo + 8;
    float dlo = __ldg(dinv + rlo);
    float dhi = __ldg(dinv + rhi);
#pragma unroll
    for (int nt = 0; nt < 4; nt++) {
        int col = (nb + nt) * 8 + qc;
        float2 o0; o0.x = c[nt][0] * dlo; o0.y = c[nt][1] * dlo;
        float2 o1; o1.x = c[nt][2] * dhi; o1.y = c[nt][3] * dhi;
        *(float2*)&HP[(size_t)rlo * 64 + col] = o0;
        *(float2*)&HP[(size_t)rhi * 64 + col] = o1;
    }

    if (APPLY_BN) {   // residual pooling of relu1 = Ah+Al (batch sorted)
        int f = tid & 63, q = tid >> 6;   // 4 groups x 16 rows
        float s = 0.0f;
        int curg = sbatch[q * 16];
#pragma unroll
        for (int rr = 0; rr < 16; rr++) {
            int r = q * 16 + rr;
            int gg = sbatch[r];
            if (gg != curg) { atomicAdd(&pool1[curg * 64 + f], s); s = 0.0f; curg = gg; }
            s += __bfloat162float(Ah[r * ASTRIDE + f]) + __bfloat162float(Al[r * ASTRIDE + f]);
        }
        atomicAdd(&pool1[curg * 64 + f], s);
    }
}

// ---------------- scan over PADDED counts ----------------
__global__ void scanA_kernel(const int* __restrict__ cnt, int* __restrict__ localex,
                             int* __restrict__ blksum) {
    __shared__ int sh[256];
    int b = blockIdx.x, t = threadIdx.x;
    int base = b * SCAN_CHUNK + t * 4;
    int v0 = (base + 0 < N_NODES) ? ((cnt[base + 0] + 3) & ~3) : 0;
    int v1 = (base + 1 < N_NODES) ? ((cnt[base + 1] + 3) & ~3) : 0;
    int v2 = (base + 2 < N_NODES) ? ((cnt[base + 2] + 3) & ~3) : 0;
    int v3 = (base + 3 < N_NODES) ? ((cnt[base + 3] + 3) & ~3) : 0;
    int s = v0 + v1 + v2 + v3;
    sh[t] = s;
    __syncthreads();
#pragma unroll
    for (int off = 1; off < 256; off <<= 1) {
        int x = (t >= off) ? sh[t - off] : 0;
        __syncthreads();
        sh[t] += x;
        __syncthreads();
    }
    int excl = sh[t] - s;
    if (t == 255) blksum[b] = sh[255];
    if (base + 0 < N_NODES) localex[base + 0] = excl;  excl += v0;
    if (base + 1 < N_NODES) localex[base + 1] = excl;  excl += v1;
    if (base + 2 < N_NODES) localex[base + 2] = excl;  excl += v2;
    if (base + 3 < N_NODES) localex[base + 3] = excl;
}

__global__ void scanC_kernel(const int* __restrict__ localex, const int* __restrict__ blksum,
                             const int* __restrict__ cnt,
                             int2* __restrict__ row2, int* __restrict__ cursor) {
    __shared__ int sh[256];
    __shared__ int pre[256];
    int t = threadIdx.x;
    int v = (t < SCAN_BLKS) ? blksum[t] : 0;
    sh[t] = v;
    __syncthreads();
#pragma unroll
    for (int off = 1; off < 256; off <<= 1) {
        int x = (t >= off) ? sh[t - off] : 0;
        __syncthreads();
        sh[t] += x;
        __syncthreads();
    }
    pre[t] = sh[t] - v;
    __syncthreads();

    int i = blockIdx.x * 256 + t;
    if (i < N_NODES) {
        int c = cnt[i];
        int r = localex[i] + pre[i >> 10];
        row2[i] = make_int2(r, (c + 3) & ~3);
        cursor[i] = r;
    }
}

__global__ void scatter_kernel(const int* __restrict__ src, const int* __restrict__ dst,
                               int* __restrict__ cursor, int* __restrict__ adj) {
    int i = blockIdx.x * blockDim.x + threadIdx.x;
    if (i >= N_EDGES / 4) return;
    int4 s = __ldg((const int4*)src + i);
    int4 d = __ldg((const int4*)dst + i);
    adj[atomicAdd(&cursor[d.x], 1)] = s.x;
    adj[atomicAdd(&cursor[d.y], 1)] = s.y;
    adj[atomicAdd(&cursor[d.z], 1)] = s.z;
    adj[atomicAdd(&cursor[d.w], 1)] = s.w;
}

// ---------------- CSR gather agg (padded, int4 idx, prefetched) + fused BN stats ------
__global__ void __launch_bounds__(256) agg_kernel(
        const int2* __restrict__ row2, const int* __restrict__ adj,
        const float* __restrict__ dinv,
        const float* __restrict__ HP, float* __restrict__ AGG,
        double* __restrict__ psums) {
    int tid  = threadIdx.x;
    int node = blockIdx.x * 16 + (tid >> 4);
    int part = tid & 15;
    const float4* Hp = (const float4*)HP;

    float4 acc = __ldg(Hp + (size_t)node * 16 + part);   // self h' (pre-scaled by dinv)
    int2 rc = __ldg(row2 + node);
    const int4* ap = (const int4*)(adj + rc.x);
    int nIt = rc.y >> 2;
    if (nIt > 0) {
        int4 s4 = __ldg(ap);
        for (int it = 0; it < nIt; it++) {
            int4 nx = (it + 1 < nIt) ? __ldg(ap + it + 1) : s4;
            float4 a = __ldg(Hp + (size_t)s4.x * 16 + part);
            float4 b = __ldg(Hp + (size_t)s4.y * 16 + part);
            float4 c = __ldg(Hp + (size_t)s4.z * 16 + part);
            float4 e = __ldg(Hp + (size_t)s4.w * 16 + part);
            acc.x += (a.x + b.x) + (c.x + e.x);
            acc.y += (a.y + b.y) + (c.y + e.y);
            acc.z += (a.z + b.z) + (c.z + e.z);
            acc.w += (a.w + b.w) + (c.w + e.w);
            s4 = nx;
        }
    }
    float dd = __ldg(dinv + node);
    acc.x *= dd; acc.y *= dd; acc.z *= dd; acc.w *= dd;
    ((float4*)AGG)[(size_t)node * 16 + part] = acc;

    __shared__ float4 s_acc[256];
    s_acc[tid] = acc;
    __syncthreads();
    if (tid < HDIM) {
        const float* sa = (const float*)s_acc;
        float s = 0.0f, sq = 0.0f;
#pragma unroll
        for (int n = 0; n < 16; n++) {
            float v = sa[n * 64 + tid];
            s += v;
            sq += v * v;
        }
        int bucket = blockIdx.x & (NBUCKET - 1);
        atomicAdd(&psums[bucket * 128 + tid], (double)s);
        atomicAdd(&psums[bucket * 128 + HDIM + tid], (double)sq);
    }
}

// ---------------- layer-1 BN finalize ----------------
__global__ void bn_finalize_kernel(const double* __restrict__ psums,
                                   const float* __restrict__ g, const float* __restrict__ be,
                                   float* __restrict__ scale, float* __restrict__ shift) {
    int f = threadIdx.x;
    if (f >= HDIM) return;
    double s = 0.0, sq = 0.0;
#pragma unroll 4
    for (int b = 0; b < NBUCKET; b++) {
        s  += psums[b * 128 + f];
        sq += psums[b * 128 + HDIM + f];
    }
    double mean = s / (double)N_NODES;
    double var  = sq / (double)N_NODES - mean * mean;
    float rs = rsqrtf((float)var + BN_EPS);
    float sc = rs * g[f];
    scale[f] = sc;
    shift[f] = (float)(-mean) * sc + be[f];
}

// ---------------- fused: BN2-finalize + BN2 apply + pool2 + residual pool1 + head -----
__global__ void __launch_bounds__(512) poolhead_kernel(
        const float* __restrict__ AGG2, const float* __restrict__ pool1,
        const double* __restrict__ psums2,
        const float* __restrict__ g2, const float* __restrict__ be2,
        const int* __restrict__ batch,
        const float* __restrict__ lw1, const float* __restrict__ lb1,
        const float* __restrict__ lw2, const float* __restrict__ lb2,
        float* __restrict__ out) {
    int g = blockIdx.x;
    int tid = threadIdx.x;

    __shared__ float sc2s[64], sh2s[64];
    __shared__ int s_start, s_end;

    if (tid >= 64 && tid < 128) {
        int f = tid - 64;
        double s = 0.0, sq = 0.0;
#pragma unroll 4
        for (int b = 0; b < NBUCKET; b++) {
            s  += psums2[b * 128 + f];
            sq += psums2[b * 128 + HDIM + f];
        }
        double mean = s / (double)N_NODES;
        double var  = sq / (double)N_NODES - mean * mean;
        float rs = rsqrtf((float)var + BN_EPS);
        float sc = rs * g2[f];
        sc2s[f] = sc;
        sh2s[f] = (float)(-mean) * sc + be2[f];
    }
    if (tid == 0) {
        int lo = 0, hi = N_NODES;
        while (lo < hi) { int mid = (lo + hi) >> 1; if (batch[mid] < g) lo = mid + 1; else hi = mid; }
        s_start = lo;
        hi = N_NODES;
        while (lo < hi) { int mid = (lo + hi) >> 1; if (batch[mid] < g + 1) lo = mid + 1; else hi = mid; }
        s_end = lo;
    }
    __syncthreads();

    int start = s_start, end = s_end;
    int f = tid & 63;
    int grp = tid >> 6;
    float sc2 = sc2s[f], sh2 = sh2s[f];
    float s = 0.0f;
#pragma unroll 2
    for (int r = start + grp; r < end; r += 8) {
        float a2 = AGG2[(size_t)r * 64 + f];
        s += fmaxf(fmaf(a2, sc2, sh2), 0.0f);
    }
    __shared__ float shm[512];
    shm[tid] = s;
    __syncthreads();

    __shared__ float p[64];
    if (grp == 0) {
        float t = 0.0f;
#pragma unroll
        for (int q = 0; q < 8; q++) t += shm[f + q * 64];
        t += __ldg(pool1 + g * 64 + f);          // residual relu1 graph sum
        int cnt = end - start;
        p[f] = t / (float)(cnt > 0 ? cnt : 1);
    }
    __syncthreads();

    __shared__ float z[32];
    __shared__ float lg[NCLS];
    if (tid < 32) {
        float acc = lb1[tid];
#pragma unroll
        for (int k = 0; k < 64; k++) acc += p[k] * lw1[k * 32 + tid];
        z[tid] = fmaxf(acc, 0.0f);
    }
    __syncthreads();
    if (tid < NCLS) {
        float acc = lb2[tid];
#pragma unroll
        for (int k = 0; k < 32; k++) acc += z[k] * lw2[k * 10 + tid];
        lg[tid] = acc;
    }
    __syncthreads();
    if (tid == 0) {
        float m = lg[0];
#pragma unroll
        for (int c = 1; c < NCLS; c++) m = fmaxf(m, lg[c]);
        float se = 0.0f;
#pragma unroll
        for (int c = 0; c < NCLS; c++) se += expf(lg[c] - m);
        float l = m + logf(se);
#pragma unroll
        for (int c = 0; c < NCLS; c++) out[g * NCLS + c] = lg[c] - l;
    }
}

// ---------------- host ----------------
extern "C" void kernel_launch(void* const* d_in, const int* in_sizes, int n_in,
                              void* d_out, int out_size) {
    const float* x     = (const float*)d_in[0];
    const int*   ei    = (const int*)  d_in[1];
    const int*   batch = (const int*)  d_in[2];
    const float* W1  = (const float*)d_in[3];
    // b1 (d_in[4]) cancels inside BatchNorm
    const float* g1  = (const float*)d_in[5];
    const float* be1 = (const float*)d_in[6];
    const float* W2  = (const float*)d_in[7];
    // b2 (d_in[8]) cancels
    const float* g2  = (const float*)d_in[9];
    const float* be2 = (const float*)d_in[10];
    const float* lw1 = (const float*)d_in[11];
    const float* lb1 = (const float*)d_in[12];
    const float* lw2 = (const float*)d_in[13];
    const float* lb2 = (const float*)d_in[14];

    const int* src = ei;
    const int* dst = ei + N_EDGES;

    float *buf1, *buf2, *buf3, *dinv, *scale, *shift, *pool1;
    int *adj, *cnt, *cursor, *localex, *blksum;
    int2* row2;
    double* psums;
    cudaGetSymbolAddress((void**)&buf1,   g_buf1);
    cudaGetSymbolAddress((void**)&buf2,   g_buf2);
    cudaGetSymbolAddress((void**)&buf3,   g_buf3);
    cudaGetSymbolAddress((void**)&adj,    g_adj);
    cudaGetSymbolAddress((void**)&cnt,    g_cnt);
    cudaGetSymbolAddress((void**)&row2,   g_row2);
    cudaGetSymbolAddress((void**)&cursor, g_cursor);
    cudaGetSymbolAddress((void**)&localex,g_localex);
    cudaGetSymbolAddress((void**)&blksum, g_blksum);
    cudaGetSymbolAddress((void**)&dinv,   g_dinv);
    cudaGetSymbolAddress((void**)&psums,  g_psums);
    cudaGetSymbolAddress((void**)&scale,  g_scale);
    cudaGetSymbolAddress((void**)&shift,  g_shift);
    cudaGetSymbolAddress((void**)&pool1,  g_pool1);

    const int TB = 256;
    const int init_blk = (ADJ_TOTAL / 4 + TB - 1) / TB;  // 1563
    const int n_blk    = (N_NODES + TB - 1) / TB;        // 782
    const int e4_blk   = (N_EDGES / 4 + TB - 1) / TB;    // 977
    const int agg_blk  = N_NODES / 16;                   // 12500
    const int gemm_blk = N_NODES / 64;                   // 3125

    // ---- degrees first so gemm1 is launch idx 3 (the ncu profile slot) ----
    init_kernel     <<<init_blk, TB>>>((int4*)adj, cnt, psums, pool1, buf1);
    deg_count_kernel<<<e4_blk, TB>>>(dst, cnt);
    dinv_kernel     <<<n_blk, TB>>>(cnt, dinv);
    gemm_hmma_kernel<false><<<gemm_blk, TB>>>(x, W1, dinv, nullptr, nullptr,
                                              nullptr, nullptr, buf1);
    scanA_kernel    <<<SCAN_BLKS, 256>>>(cnt, localex, blksum);
    scanC_kernel    <<<n_blk, 256>>>(localex, blksum, cnt, row2, cursor);
    scatter_kernel  <<<e4_blk, TB>>>(src, dst, cursor, adj);

    // ---- layer 1 ----
    agg_kernel          <<<agg_blk, TB>>>(row2, adj, dinv, buf1, buf2, psums);
    bn_finalize_kernel  <<<1, 64>>>(psums, g1, be1, scale, shift);

    // ---- layer 2 (BN1+relu + residual pooling fused into GEMM) ----
    gemm_hmma_kernel<true><<<gemm_blk, TB>>>(buf2, W2, dinv, scale, shift,
                                             batch, pool1, buf1);
    agg_kernel          <<<agg_blk, TB>>>(row2, adj, dinv, buf1, buf3, psums + PSUM_STRIDE);

    // ---- fused BN2-finalize + apply + pool + head ----
    poolhead_kernel<<<NGRAPH, 512>>>(buf3, pool1, psums + PSUM_STRIDE,
                                     g2, be2, batch, lw1, lb1, lw2, lb2, (float*)d_out);
}

// round 16
// speedup vs baseline: 1.3025x; 1.0172x over previous
#include <cuda_runtime.h>
#include <cuda_bf16.h>
#include <math.h>

#define N_NODES 200000
#define N_EDGES 1000000
#define HDIM    64
#define NGRAPH  512
#define NCLS    10
#define BN_EPS  1e-5f

#define SCAN_CHUNK 1024
#define SCAN_BLKS  ((N_NODES + SCAN_CHUNK - 1) / SCAN_CHUNK)   // 196
#define NBUCKET 64
#define PSUM_STRIDE (NBUCKET * 2 * HDIM)            // 8192 doubles per layer
#define ADJ_TOTAL (N_EDGES + 3 * N_NODES)           // padded adjacency capacity

#define ASTRIDE 72      // bf16 elements per smem row (144B: conflict-free ldmatrix)

typedef unsigned int uint32;

// ---------------- static device scratch ----------------
__device__ __align__(256) float  g_buf1[(size_t)(N_NODES + 1) * HDIM]; // h' (row N = 0)
__device__ __align__(256) float  g_buf2[(size_t)N_NODES * HDIM];       // AGG layer 1
__device__ __align__(256) float  g_buf3[(size_t)N_NODES * HDIM];       // AGG layer 2
__device__ __align__(256) int    g_adj[ADJ_TOTAL];
__device__ __align__(256) int    g_cnt[N_NODES];
__device__ __align__(256) int2   g_row2[N_NODES];
__device__ __align__(256) int    g_cursor[N_NODES];
__device__ __align__(256) int    g_localex[N_NODES];
__device__ __align__(16)  int    g_blksum[256];
__device__ __align__(256) float  g_dinv[N_NODES];
__device__ __align__(256) double g_psums[2 * PSUM_STRIDE];
__device__ __align__(16)  float  g_scale[HDIM];
__device__ __align__(16)  float  g_shift[HDIM];
__device__ __align__(256) float  g_pool1[NGRAPH * HDIM];
// pre-split, pre-transposed weights: [n][k] bf16, packed (64*64 each)
__device__ __align__(256) __nv_bfloat16 g_wt[4 * HDIM * HDIM];  // W1h,W1l,W2h,W2l

// ---------------- warp-MMA helpers ----------------
__device__ __forceinline__ uint32 smem_u32(const void* p) {
    uint32 a;
    asm("{ .reg .u64 t; cvta.to.shared.u64 t, %1; cvt.u32.u64 %0, t; }" : "=r"(a) : "l"(p));
    return a;
}
#define LDSM4(r, addr) \
    asm volatile("ldmatrix.sync.aligned.m8n8.x4.shared.b16 {%0, %1, %2, %3}, [%4];" \
        : "=r"((r)[0]), "=r"((r)[1]), "=r"((r)[2]), "=r"((r)[3]) : "r"(addr))
#define MMA16816(c, a, b0, b1) \
    asm volatile("mma.sync.aligned.m16n8k16.row.col.f32.bf16.bf16.f32 " \
        "{%0, %1, %2, %3}, {%4, %5, %6, %7}, {%8, %9}, {%0, %1, %2, %3};" \
        : "+f"((c)[0]), "+f"((c)[1]), "+f"((c)[2]), "+f"((c)[3]) \
        : "r"((a)[0]), "r"((a)[1]), "r"((a)[2]), "r"((a)[3]), "r"(b0), "r"(b1))

// ---------------- init ----------------
__global__ void init_kernel(int4* __restrict__ adj4, int* __restrict__ cnt,
                            double* __restrict__ psums, float* __restrict__ pool1,
                            float* __restrict__ buf1) {
    int i = blockIdx.x * blockDim.x + threadIdx.x;
    if (i < ADJ_TOTAL / 4) adj4[i] = make_int4(N_NODES, N_NODES, N_NODES, N_NODES);
    if (i < N_NODES) cnt[i] = 0;
    if (i < 2 * PSUM_STRIDE) psums[i] = 0.0;
    if (i < NGRAPH * HDIM) pool1[i] = 0.0f;
    if (i < HDIM) buf1[(size_t)N_NODES * HDIM + i] = 0.0f;  // zero row for dummies
}

__global__ void deg_count_kernel(const int* __restrict__ dst, int* __restrict__ cnt) {
    int i = blockIdx.x * blockDim.x + threadIdx.x;
    if (i >= N_EDGES / 4) return;
    int4 d = __ldg((const int4*)dst + i);
    atomicAdd(&cnt[d.x], 1);
    atomicAdd(&cnt[d.y], 1);
    atomicAdd(&cnt[d.z], 1);
    atomicAdd(&cnt[d.w], 1);
}

// dinv + W pre-split/transpose (last 2 blocks handle W1/W2)
__global__ void dinv_wsplit_kernel(const int* __restrict__ cnt, float* __restrict__ dinv,
                                   int n_blk, const float* __restrict__ W1,
                                   const float* __restrict__ W2,
                                   __nv_bfloat16* __restrict__ wt) {
    int b = blockIdx.x;
    if (b < n_blk) {
        int i = b * blockDim.x + threadIdx.x;
        if (i < N_NODES) dinv[i] = rsqrtf((float)(cnt[i] + 1));
        return;
    }
    int which = b - n_blk;                       // 0: W1, 1: W2
    const float* W = which ? W2 : W1;
    __nv_bfloat16* wh = wt + which * 2 * HDIM * HDIM;
    __nv_bfloat16* wl = wh + HDIM * HDIM;
#pragma unroll
    for (int j = 0; j < 16; j++) {
        int i = threadIdx.x + j * 256;           // 0..4095
        int k = i >> 6, n = i & 63;
        float w = __ldg(W + i);
        __nv_bfloat16 h = __float2bfloat16(w);
        wh[n * 64 + k] = h;
        wl[n * 64 + k] = __float2bfloat16(w - __bfloat162float(h));
    }
}

// ---------------- HMMA GEMM: HP = (X@W)*dinv, bf16 3-product split ----------------
// 256 threads = 8 warps; warp w: mtile = w>>1 (16 rows), ntiles (w&1)*4..+3 (32 cols).
// APPLY_BN: X := relu(BN1(X)) on load + fused residual pooling into pool1.
template <bool APPLY_BN>
__global__ void __launch_bounds__(256) gemm_hmma_kernel(
        const float* __restrict__ X,
        const __nv_bfloat16* __restrict__ Wth, const __nv_bfloat16* __restrict__ Wtl,
        const float* __restrict__ dinv,
        const float* __restrict__ scale, const float* __restrict__ shift,
        const int* __restrict__ batch, float* __restrict__ pool1,
        float* __restrict__ HP) {
    __shared__ __align__(16) __nv_bfloat16 Ah[64 * ASTRIDE];
    __shared__ __align__(16) __nv_bfloat16 Al[64 * ASTRIDE];
    __shared__ __align__(16) __nv_bfloat16 Bh[64 * ASTRIDE];   // Wt[n][k]
    __shared__ __align__(16) __nv_bfloat16 Bl[64 * ASTRIDE];
    __shared__ int sbatch[64];

    int tid  = threadIdx.x;
    int row0 = blockIdx.x * 64;   // 200000 = 64*3125 exact

    if (APPLY_BN && tid < 64) sbatch[tid] = batch[row0 + tid];

    // B fill: copy pre-split transposed W into padded smem (int4 = 8 bf16)
    const int4* WH4 = (const int4*)Wth;
    const int4* WL4 = (const int4*)Wtl;
#pragma unroll
    for (int p = 0; p < 2; p++) {
        int idx8 = tid + p * 256;                // 0..511
        int n = idx8 >> 3, kc = idx8 & 7;
        *(int4*)&Bh[n * ASTRIDE + kc * 8] = __ldg(WH4 + idx8);
        *(int4*)&Bl[n * ASTRIDE + kc * 8] = __ldg(WL4 + idx8);
    }

    // A fill: 8 contiguous floats per thread-pass -> one STS.128 each for hi/lo
#pragma unroll
    for (int p = 0; p < 2; p++) {
        int idx8 = tid + p * 256;                // 0..511
        int r = idx8 >> 3, c8 = idx8 & 7;
        const float4* xp = (const float4*)X + (size_t)(row0 + r) * 16 + c8 * 2;
        float4 v0 = __ldg(xp), v1 = __ldg(xp + 1);
        if (APPLY_BN) {
            float4 s0 = __ldg((const float4*)scale + c8 * 2);
            float4 s1 = __ldg((const float4*)scale + c8 * 2 + 1);
            float4 t0 = __ldg((const float4*)shift + c8 * 2);
            float4 t1 = __ldg((const float4*)shift + c8 * 2 + 1);
            v0.x = fmaxf(fmaf(v0.x, s0.x, t0.x), 0.0f);
            v0.y = fmaxf(fmaf(v0.y, s0.y, t0.y), 0.0f);
            v0.z = fmaxf(fmaf(v0.z, s0.z, t0.z), 0.0f);
            v0.w = fmaxf(fmaf(v0.w, s0.w, t0.w), 0.0f);
            v1.x = fmaxf(fmaf(v1.x, s1.x, t1.x), 0.0f);
            v1.y = fmaxf(fmaf(v1.y, s1.y, t1.y), 0.0f);
            v1.z = fmaxf(fmaf(v1.z, s1.z, t1.z), 0.0f);
            v1.w = fmaxf(fmaf(v1.w, s1.w, t1.w), 0.0f);
        }
        float fx0 = v0.x, fx1 = v0.y, fx2 = v0.z, fx3 = v0.w;
        float fx4 = v1.x, fx5 = v1.y, fx6 = v1.z, fx7 = v1.w;
        uint4 hv, lv;
        uint32* hp = (uint32*)&hv;
        uint32* lp = (uint32*)&lv;
#define CVT_PAIR(slot, a, b) { \
            __nv_bfloat16 ha = __float2bfloat16(a), hb = __float2bfloat16(b); \
            __nv_bfloat162 hh; hh.x = ha; hh.y = hb; \
            hp[slot] = *(uint32*)&hh; \
            __nv_bfloat162 ll; \
            ll.x = __float2bfloat16((a) - __bfloat162float(ha)); \
            ll.y = __float2bfloat16((b) - __bfloat162float(hb)); \
            lp[slot] = *(uint32*)&ll; }
        CVT_PAIR(0, fx0, fx1)
        CVT_PAIR(1, fx2, fx3)
        CVT_PAIR(2, fx4, fx5)
        CVT_PAIR(3, fx6, fx7)
#undef CVT_PAIR
        *(uint4*)&Ah[r * ASTRIDE + c8 * 8] = hv;
        *(uint4*)&Al[r * ASTRIDE + c8 * 8] = lv;
    }
    __syncthreads();

    int wid = tid >> 5, lane = tid & 31;
    int mt = wid >> 1;            // 0..3
    int nb = (wid & 1) * 4;       // ntile base (cols nb*8)

    uint32 aH = smem_u32(Ah) + ((mt * 16 + (lane & 15)) * ASTRIDE + ((lane >> 4) << 3)) * 2;
    uint32 aL = aH + (uint32)(Al - Ah) * 2;
    int quad = lane >> 3;
    uint32 bRow = (nb * 8 + ((quad >> 1) << 3) + (lane & 7)) * ASTRIDE + ((quad & 1) << 3);
    uint32 bH1 = smem_u32(Bh) + bRow * 2;
    uint32 bH2 = bH1 + 16 * ASTRIDE * 2;
    uint32 bL1 = smem_u32(Bl) + bRow * 2;
    uint32 bL2 = bL1 + 16 * ASTRIDE * 2;

    float c[4][4];
#pragma unroll
    for (int i = 0; i < 4; i++)
#pragma unroll
        for (int j = 0; j < 4; j++) c[i][j] = 0.0f;

#pragma unroll
    for (int ks = 0; ks < 4; ks++) {
        uint32 ko = ks * 32;   // 16 bf16 = 32 bytes
        uint32 ah[4], al[4], bh01[4], bh23[4], bl01[4], bl23[4];
        LDSM4(ah, aH + ko);
        LDSM4(al, aL + ko);
        LDSM4(bh01, bH1 + ko);
        LDSM4(bh23, bH2 + ko);
        LDSM4(bl01, bL1 + ko);
        LDSM4(bl23, bL2 + ko);
        MMA16816(c[0], ah, bh01[0], bh01[1]);
        MMA16816(c[1], ah, bh01[2], bh01[3]);
        MMA16816(c[2], ah, bh23[0], bh23[1]);
        MMA16816(c[3], ah, bh23[2], bh23[3]);
        MMA16816(c[0], ah, bl01[0], bl01[1]);
        MMA16816(c[1], ah, bl01[2], bl01[3]);
        MMA16816(c[2], ah, bl23[0], bl23[1]);
        MMA16816(c[3], ah, bl23[2], bl23[3]);
        MMA16816(c[0], al, bh01[0], bh01[1]);
        MMA16816(c[1], al, bh01[2], bh01[3]);
        MMA16816(c[2], al, bh23[0], bh23[1]);
        MMA16816(c[3], al, bh23[2], bh23[3]);
    }

    // epilogue: scale by dinv[row], store float2 per accum pair
    int qr = lane >> 2;           // 0..7
    int qc = (lane & 3) * 2;
    int rlo = row0 + mt * 16 + qr;
    int rhi = rlo + 8;
    float dlo = __ldg(dinv + rlo);
    float dhi = __ldg(dinv + rhi);
#pragma unroll
    for (int nt = 0; nt < 4; nt++) {
        int col = (nb + nt) * 8 + qc;
        float2 o0; o0.x = c[nt][0] * dlo; o0.y = c[nt][1] * dlo;
        float2 o1; o1.x = c[nt][2] * dhi; o1.y = c[nt][3] * dhi;
        *(float2*)&HP[(size_t)rlo * 64 + col] = o0;
        *(float2*)&HP[(size_t)rhi * 64 + col] = o1;
    }

    if (APPLY_BN) {   // residual pooling of relu1 = Ah+Al (batch sorted)
        int f = tid & 63, q = tid >> 6;   // 4 groups x 16 rows
        float s = 0.0f;
        int curg = sbatch[q * 16];
#pragma unroll
        for (int rr = 0; rr < 16; rr++) {
            int r = q * 16 + rr;
            int gg = sbatch[r];
            if (gg != curg) { atomicAdd(&pool1[curg * 64 + f], s); s = 0.0f; curg = gg; }
            s += __bfloat162float(Ah[r * ASTRIDE + f]) + __bfloat162float(Al[r * ASTRIDE + f]);
        }
        atomicAdd(&pool1[curg * 64 + f], s);
    }
}

// ---------------- scan over PADDED counts ----------------
__global__ void scanA_kernel(const int* __restrict__ cnt, int* __restrict__ localex,
                             int* __restrict__ blksum) {
    __shared__ int sh[256];
    int b = blockIdx.x, t = threadIdx.x;
    int base = b * SCAN_CHUNK + t * 4;
    int v0 = (base + 0 < N_NODES) ? ((cnt[base + 0] + 3) & ~3) : 0;
    int v1 = (base + 1 < N_NODES) ? ((cnt[base + 1] + 3) & ~3) : 0;
    int v2 = (base + 2 < N_NODES) ? ((cnt[base + 2] + 3) & ~3) : 0;
    int v3 = (base + 3 < N_NODES) ? ((cnt[base + 3] + 3) & ~3) : 0;
    int s = v0 + v1 + v2 + v3;
    sh[t] = s;
    __syncthreads();
#pragma unroll
    for (int off = 1; off < 256; off <<= 1) {
        int x = (t >= off) ? sh[t - off] : 0;
        __syncthreads();
        sh[t] += x;
        __syncthreads();
    }
    int excl = sh[t] - s;
    if (t == 255) blksum[b] = sh[255];
    if (base + 0 < N_NODES) localex[base + 0] = excl;  excl += v0;
    if (base + 1 < N_NODES) localex[base + 1] = excl;  excl += v1;
    if (base + 2 < N_NODES) localex[base + 2] = excl;  excl += v2;
    if (base + 3 < N_NODES) localex[base + 3] = excl;
}

__global__ void scanC_kernel(const int* __restrict__ localex, const int* __restrict__ blksum,
                             const int* __restrict__ cnt,
                             int2* __restrict__ row2, int* __restrict__ cursor) {
    __shared__ int sh[256];
    __shared__ int pre[256];
    int t = threadIdx.x;
    int v = (t < SCAN_BLKS) ? blksum[t] : 0;
    sh[t] = v;
    __syncthreads();
#pragma unroll
    for (int off = 1; off < 256; off <<= 1) {
        int x = (t >= off) ? sh[t - off] : 0;
        __syncthreads();
        sh[t] += x;
        __syncthreads();
    }
    pre[t] = sh[t] - v;
    __syncthreads();

    int i = blockIdx.x * 256 + t;
    if (i < N_NODES) {
        int c = cnt[i];
        int r = localex[i] + pre[i >> 10];
        row2[i] = make_int2(r, (c + 3) & ~3);
        cursor[i] = r;
    }
}

__global__ void scatter_kernel(const int* __restrict__ src, const int* __restrict__ dst,
                               int* __restrict__ cursor, int* __restrict__ adj) {
    int i = blockIdx.x * blockDim.x + threadIdx.x;
    if (i >= N_EDGES / 4) return;
    int4 s = __ldg((const int4*)src + i);
    int4 d = __ldg((const int4*)dst + i);
    adj[atomicAdd(&cursor[d.x], 1)] = s.x;
    adj[atomicAdd(&cursor[d.y], 1)] = s.y;
    adj[atomicAdd(&cursor[d.z], 1)] = s.z;
    adj[atomicAdd(&cursor[d.w], 1)] = s.w;
}

// ---------------- CSR gather agg (padded, int4 idx, prefetched) + fused BN stats ------
__global__ void __launch_bounds__(256) agg_kernel(
        const int2* __restrict__ row2, const int* __restrict__ adj,
        const float* __restrict__ dinv,
        const float* __restrict__ HP, float* __restrict__ AGG,
        double* __restrict__ psums) {
    int tid  = threadIdx.x;
    int node = blockIdx.x * 16 + (tid >> 4);
    int part = tid & 15;
    const float4* Hp = (const float4*)HP;

    float4 acc = __ldg(Hp + (size_t)node * 16 + part);
    int2 rc = __ldg(row2 + node);
    const int4* ap = (const int4*)(adj + rc.x);
    int nIt = rc.y >> 2;
    if (nIt > 0) {
        int4 s4 = __ldg(ap);
        for (int it = 0; it < nIt; it++) {
            int4 nx = (it + 1 < nIt) ? __ldg(ap + it + 1) : s4;
            float4 a = __ldg(Hp + (size_t)s4.x * 16 + part);
            float4 b = __ldg(Hp + (size_t)s4.y * 16 + part);
            float4 c = __ldg(Hp + (size_t)s4.z * 16 + part);
            float4 e = __ldg(Hp + (size_t)s4.w * 16 + part);
            acc.x += (a.x + b.x) + (c.x + e.x);
            acc.y += (a.y + b.y) + (c.y + e.y);
            acc.z += (a.z + b.z) + (c.z + e.z);
            acc.w += (a.w + b.w) + (c.w + e.w);
            s4 = nx;
        }
    }
    float dd = __ldg(dinv + node);
    acc.x *= dd; acc.y *= dd; acc.z *= dd; acc.w *= dd;
    ((float4*)AGG)[(size_t)node * 16 + part] = acc;

    __shared__ float4 s_acc[256];
    s_acc[tid] = acc;
    __syncthreads();
    if (tid < HDIM) {
        const float* sa = (const float*)s_acc;
        float s = 0.0f, sq = 0.0f;
#pragma unroll
        for (int n = 0; n < 16; n++) {
            float v = sa[n * 64 + tid];
            s += v;
            sq += v * v;
        }
        int bucket = blockIdx.x & (NBUCKET - 1);
        atomicAdd(&psums[bucket * 128 + tid], (double)s);
        atomicAdd(&psums[bucket * 128 + HDIM + tid], (double)sq);
    }
}

// ---------------- layer-1 BN finalize ----------------
__global__ void bn_finalize_kernel(const double* __restrict__ psums,
                                   const float* __restrict__ g, const float* __restrict__ be,
                                   float* __restrict__ scale, float* __restrict__ shift) {
    int f = threadIdx.x;
    if (f >= HDIM) return;
    double s = 0.0, sq = 0.0;
#pragma unroll 4
    for (int b = 0; b < NBUCKET; b++) {
        s  += psums[b * 128 + f];
        sq += psums[b * 128 + HDIM + f];
    }
    double mean = s / (double)N_NODES;
    double var  = sq / (double)N_NODES - mean * mean;
    float rs = rsqrtf((float)var + BN_EPS);
    float sc = rs * g[f];
    scale[f] = sc;
    shift[f] = (float)(-mean) * sc + be[f];
}

// ---------------- fused: BN2-finalize + BN2 apply + pool2 + residual pool1 + head -----
__global__ void __launch_bounds__(512) poolhead_kernel(
        const float* __restrict__ AGG2, const float* __restrict__ pool1,
        const double* __restrict__ psums2,
        const float* __restrict__ g2, const float* __restrict__ be2,
        const int* __restrict__ batch,
        const float* __restrict__ lw1, const float* __restrict__ lb1,
        const float* __restrict__ lw2, const float* __restrict__ lb2,
        float* __restrict__ out) {
    int g = blockIdx.x;
    int tid = threadIdx.x;

    __shared__ float sc2s[64], sh2s[64];
    __shared__ int s_start, s_end;

    if (tid >= 64 && tid < 128) {
        int f = tid - 64;
        double s = 0.0, sq = 0.0;
#pragma unroll 4
        for (int b = 0; b < NBUCKET; b++) {
            s  += psums2[b * 128 + f];
            sq += psums2[b * 128 + HDIM + f];
        }
        double mean = s / (double)N_NODES;
        double var  = sq / (double)N_NODES - mean * mean;
        float rs = rsqrtf((float)var + BN_EPS);
        float sc = rs * g2[f];
        sc2s[f] = sc;
        sh2s[f] = (float)(-mean) * sc + be2[f];
    }
    if (tid == 0) {
        int lo = 0, hi = N_NODES;
        while (lo < hi) { int mid = (lo + hi) >> 1; if (batch[mid] < g) lo = mid + 1; else hi = mid; }
        s_start = lo;
        hi = N_NODES;
        while (lo < hi) { int mid = (lo + hi) >> 1; if (batch[mid] < g + 1) lo = mid + 1; else hi = mid; }
        s_end = lo;
    }
    __syncthreads();

    int start = s_start, end = s_end;
    int f = tid & 63;
    int grp = tid >> 6;
    float sc2 = sc2s[f], sh2 = sh2s[f];
    float s = 0.0f;
#pragma unroll 2
    for (int r = start + grp; r < end; r += 8) {
        float a2 = AGG2[(size_t)r * 64 + f];
        s += fmaxf(fmaf(a2, sc2, sh2), 0.0f);
    }
    __shared__ float shm[512];
    shm[tid] = s;
    __syncthreads();

    __shared__ float p[64];
    if (grp == 0) {
        float t = 0.0f;
#pragma unroll
        for (int q = 0; q < 8; q++) t += shm[f + q * 64];
        t += __ldg(pool1 + g * 64 + f);          // residual relu1 graph sum
        int cnt = end - start;
        p[f] = t / (float)(cnt > 0 ? cnt : 1);
    }
    __syncthreads();

    __shared__ float z[32];
    __shared__ float lg[NCLS];
    if (tid < 32) {
        float acc = lb1[tid];
#pragma unroll
        for (int k = 0; k < 64; k++) acc += p[k] * lw1[k * 32 + tid];
        z[tid] = fmaxf(acc, 0.0f);
    }
    __syncthreads();
    if (tid < NCLS) {
        float acc = lb2[tid];
#pragma unroll
        for (int k = 0; k < 32; k++) acc += z[k] * lw2[k * 10 + tid];
        lg[tid] = acc;
    }
    __syncthreads();
    if (tid == 0) {
        float m = lg[0];
#pragma unroll
        for (int c = 1; c < NCLS; c++) m = fmaxf(m, lg[c]);
        float se = 0.0f;
#pragma unroll
        for (int c = 0; c < NCLS; c++) se += expf(lg[c] - m);
        float l = m + logf(se);
#pragma unroll
        for (int c = 0; c < NCLS; c++) out[g * NCLS + c] = lg[c] - l;
    }
}

// ---------------- host ----------------
extern "C" void kernel_launch(void* const* d_in, const int* in_sizes, int n_in,
                              void* d_out, int out_size) {
    const float* x     = (const float*)d_in[0];
    const int*   ei    = (const int*)  d_in[1];
    const int*   batch = (const int*)  d_in[2];
    const float* W1  = (const float*)d_in[3];
    // b1 (d_in[4]) cancels inside BatchNorm
    const float* g1  = (const float*)d_in[5];
    const float* be1 = (const float*)d_in[6];
    const float* W2  = (const float*)d_in[7];
    // b2 (d_in[8]) cancels
    const float* g2  = (const float*)d_in[9];
    const float* be2 = (const float*)d_in[10];
    const float* lw1 = (const float*)d_in[11];
    const float* lb1 = (const float*)d_in[12];
    const float* lw2 = (const float*)d_in[13];
    const float* lb2 = (const float*)d_in[14];

    const int* src = ei;
    const int* dst = ei + N_EDGES;

    float *buf1, *buf2, *buf3, *dinv, *scale, *shift, *pool1;
    int *adj, *cnt, *cursor, *localex, *blksum;
    int2* row2;
    double* psums;
    __nv_bfloat16* wt;
    cudaGetSymbolAddress((void**)&buf1,   g_buf1);
    cudaGetSymbolAddress((void**)&buf2,   g_buf2);
    cudaGetSymbolAddress((void**)&buf3,   g_buf3);
    cudaGetSymbolAddress((void**)&adj,    g_adj);
    cudaGetSymbolAddress((void**)&cnt,    g_cnt);
    cudaGetSymbolAddress((void**)&row2,   g_row2);
    cudaGetSymbolAddress((void**)&cursor, g_cursor);
    cudaGetSymbolAddress((void**)&localex,g_localex);
    cudaGetSymbolAddress((void**)&blksum, g_blksum);
    cudaGetSymbolAddress((void**)&dinv,   g_dinv);
    cudaGetSymbolAddress((void**)&psums,  g_psums);
    cudaGetSymbolAddress((void**)&scale,  g_scale);
    cudaGetSymbolAddress((void**)&shift,  g_shift);
    cudaGetSymbolAddress((void**)&pool1,  g_pool1);
    cudaGetSymbolAddress((void**)&wt,     g_wt);

    const __nv_bfloat16* w1h = wt;
    const __nv_bfloat16* w1l = wt + HDIM * HDIM;
    const __nv_bfloat16* w2h = wt + 2 * HDIM * HDIM;
    const __nv_bfloat16* w2l = wt + 3 * HDIM * HDIM;

    const int TB = 256;
    const int init_blk = (ADJ_TOTAL / 4 + TB - 1) / TB;  // 1563
    const int n_blk    = (N_NODES + TB - 1) / TB;        // 782
    const int e4_blk   = (N_EDGES / 4 + TB - 1) / TB;    // 977
    const int agg_blk  = N_NODES / 16;                   // 12500
    const int gemm_blk = N_NODES / 64;                   // 3125

    // ---- degrees + W split first; gemm1 at launch idx 3 (the ncu profile slot) ----
    init_kernel      <<<init_blk, TB>>>((int4*)adj, cnt, psums, pool1, buf1);
    deg_count_kernel <<<e4_blk, TB>>>(dst, cnt);
    dinv_wsplit_kernel<<<n_blk + 2, TB>>>(cnt, dinv, n_blk, W1, W2, wt);
    gemm_hmma_kernel<false><<<gemm_blk, TB>>>(x, w1h, w1l, dinv, nullptr, nullptr,
                                              nullptr, nullptr, buf1);
    scanA_kernel     <<<SCAN_BLKS, 256>>>(cnt, localex, blksum);
    scanC_kernel     <<<n_blk, 256>>>(localex, blksum, cnt, row2, cursor);
    scatter_kernel   <<<e4_blk, TB>>>(src, dst, cursor, adj);

    // ---- layer 1 ----
    agg_kernel          <<<agg_blk, TB>>>(row2, adj, dinv, buf1, buf2, psums);
    bn_finalize_kernel  <<<1, 64>>>(psums, g1, be1, scale, shift);

    // ---- layer 2 (BN1+relu + residual pooling fused into GEMM) ----
    gemm_hmma_kernel<true><<<gemm_blk, TB>>>(buf2, w2h, w2l, dinv, scale, shift,
                                             batch, pool1, buf1);
    agg_kernel          <<<agg_blk, TB>>>(row2, adj, dinv, buf1, buf3, psums + PSUM_STRIDE);

    // ---- fused BN2-finalize + apply + pool + head ----
    poolhead_kernel<<<NGRAPH, 512>>>(buf3, pool1, psums + PSUM_STRIDE,
                                     g2, be2, batch, lw1, lb1, lw2, lb2, (float*)d_out);
}